// round 13
// baseline (speedup 1.0000x reference)
#include <cuda_runtime.h>
#include <cuda_fp16.h>
#include <math.h>
#include <stdint.h>

// Problem constants
#define Bn  2
#define Ln  2048
#define Dn  1024
#define Hn  16
#define DHn 64
#define BHn (Bn*Hn)   // 32
#define Mrows (Bn*Ln) // 4096

// fp16 copies of inputs (prepass) + fp16 q/k/v scratch in [bh][l][dh].
__device__ __half g_xh[(size_t)Mrows*Dn];        // 8 MB
__device__ __half g_wh[3][(size_t)Dn*Dn];        // 6 MB
__device__ __half g_q[(size_t)BHn*Ln*DHn];       // 8 MB total q/k/v
__device__ __half g_k[(size_t)BHn*Ln*DHn];
__device__ __half g_v[(size_t)BHn*Ln*DHn];

// ---------------------------------------------------------------------------
// helpers
// ---------------------------------------------------------------------------
__device__ __forceinline__ uint32_t pack_h2(float x, float y) {
    __half2 h = __floats2half2_rn(x, y);
    return *(uint32_t*)&h;
}

// D += A(16x16,row) * B(16x8,col), fp16 inputs, fp32 accum
__device__ __forceinline__ void mma_f16(float d[4], const uint32_t a[4], const uint32_t b[2]) {
    asm volatile(
        "mma.sync.aligned.m16n8k16.row.col.f32.f16.f16.f32 "
        "{%0,%1,%2,%3}, {%4,%5,%6,%7}, {%8,%9}, {%0,%1,%2,%3};\n"
        : "+f"(d[0]), "+f"(d[1]), "+f"(d[2]), "+f"(d[3])
        : "r"(a[0]), "r"(a[1]), "r"(a[2]), "r"(a[3]),
          "r"(b[0]), "r"(b[1]));
}

// ---------------------------------------------------------------------------
// Pre-pass: fp32 -> fp16 conversion (vectorized, grid-stride)
// ---------------------------------------------------------------------------
__global__ void cvt_f32_f16(const float* __restrict__ src, __half* __restrict__ dst, int n4)
{
    int i = blockIdx.x * blockDim.x + threadIdx.x;
    int stride = gridDim.x * blockDim.x;
    for (; i < n4; i += stride) {
        float4 v = ((const float4*)src)[i];
        uint2 u = { pack_h2(v.x, v.y), pack_h2(v.z, v.w) };
        *(uint2*)&dst[(size_t)i * 4] = u;
    }
}

// ---------------------------------------------------------------------------
// QKV projection: y = x @ W^T + b, fp16 in (prepass), fp16 scratch out.
// Round-12 geometry exactly: block tile 128x128, BK=32, single-buffered smem
// [row][pair] stride 20, uint2 stores; 8 warps (2m x 4n), 4x4 m16n8k16 frags.
// Only the epilogue store dtype changed (packed half2 instead of float2).
// ---------------------------------------------------------------------------
__global__ __launch_bounds__(256) void qkv_gemm_f16(
    const float* __restrict__ bq, const float* __restrict__ bk,
    const float* __restrict__ bv)
{
    __shared__ uint32_t As[128][20];   // 10 KB
    __shared__ uint32_t Bs[128][20];   // 10 KB

    const __half* W = g_wh[blockIdx.z];
    const float* bias; __half* dst;
    if (blockIdx.z == 0)      { bias = bq; dst = g_q; }
    else if (blockIdx.z == 1) { bias = bk; dst = g_k; }
    else                      { bias = bv; dst = g_v; }

    const int tid  = threadIdx.x;
    const int lane = tid & 31;
    const int warp = tid >> 5;
    const int wm   = warp >> 2;      // 0..1
    const int wn   = warp & 3;       // 0..3
    const int rowBase = blockIdx.y * 128;
    const int colBase = blockIdx.x * 128;

    float acc[4][4][4];
    #pragma unroll
    for (int mt = 0; mt < 4; mt++)
        #pragma unroll
        for (int nt = 0; nt < 4; nt++)
            #pragma unroll
            for (int i = 0; i < 4; i++) acc[mt][nt][i] = 0.f;

    for (int kb = 0; kb < Dn; kb += 32) {
        // loader: 4 iters x 256 threads = 1024 uint2 (4 halfs) per matrix
        uint2 a_reg[4], b_reg[4];
        #pragma unroll
        for (int i = 0; i < 4; i++) {
            int idx = i * 256 + tid;
            int row = idx >> 3, c4 = idx & 7;
            a_reg[i] = *(const uint2*)&g_xh[(size_t)(rowBase + row) * Dn + kb + c4 * 4];
            b_reg[i] = *(const uint2*)&W[(size_t)(colBase + row) * Dn + kb + c4 * 4];
        }
        __syncthreads();   // previous chunk's compute done before overwrite
        #pragma unroll
        for (int i = 0; i < 4; i++) {
            int idx = i * 256 + tid;
            int row = idx >> 3, c4 = idx & 7;
            *(uint2*)&As[row][c4 * 2] = a_reg[i];
            *(uint2*)&Bs[row][c4 * 2] = b_reg[i];
        }
        __syncthreads();

        #pragma unroll
        for (int kc = 0; kc < 2; kc++) {
            const int c = kc * 8 + (lane & 3);
            uint32_t af[4][4];
            #pragma unroll
            for (int mt = 0; mt < 4; mt++) {
                int r = wm * 64 + mt * 16 + (lane >> 2);
                af[mt][0] = As[r][c];
                af[mt][1] = As[r + 8][c];
                af[mt][2] = As[r][c + 4];
                af[mt][3] = As[r + 8][c + 4];
            }
            uint32_t bf[4][2];
            #pragma unroll
            for (int nt = 0; nt < 4; nt++) {
                int n = wn * 32 + nt * 8 + (lane >> 2);
                bf[nt][0] = Bs[n][c];
                bf[nt][1] = Bs[n][c + 4];
            }
            #pragma unroll
            for (int mt = 0; mt < 4; mt++)
                #pragma unroll
                for (int nt = 0; nt < 4; nt++)
                    mma_f16(acc[mt][nt], af[mt], bf[nt]);
        }
    }

    // epilogue: bias + head relayout into [bh][l][dh], packed fp16 store
    #pragma unroll
    for (int nt = 0; nt < 4; nt++) {
        int gcol = colBase + wn * 32 + nt * 8 + 2 * (lane & 3);
        int h  = gcol >> 6;
        int dh = gcol & (DHn - 1);
        float bb0 = bias[gcol], bb1 = bias[gcol + 1];
        #pragma unroll
        for (int mt = 0; mt < 4; mt++) {
            int grow = rowBase + wm * 64 + mt * 16 + (lane >> 2);
            {
                int b = grow >> 11, l = grow & (Ln - 1);
                uint32_t v = pack_h2(acc[mt][nt][0] + bb0, acc[mt][nt][1] + bb1);
                *(uint32_t*)&dst[((size_t)(b * Hn + h) * Ln + l) * DHn + dh] = v;
            }
            {
                int grow2 = grow + 8;
                int b = grow2 >> 11, l = grow2 & (Ln - 1);
                uint32_t v = pack_h2(acc[mt][nt][2] + bb0, acc[mt][nt][3] + bb1);
                *(uint32_t*)&dst[((size_t)(b * Hn + h) * Ln + l) * DHn + dh] = v;
            }
        }
    }
}

// ---------------------------------------------------------------------------
// Flash attention (causal), fp16 m16n8k16 MMA + register prefetch of K/V.
// Round-12 kernel with fp16 K/V/Q source: prefetch is uint2 (half regs),
// K commit is a raw copy (no cvt), V transpose stores halfs directly.
// Longest-first scheduling kept.
// ---------------------------------------------------------------------------
__global__ __launch_bounds__(128) void attn_f16(float* __restrict__ out)
{
    __shared__ uint32_t QP[64][36];    // Q (32 dh-pairs), later P (16 key-pairs)
    __shared__ uint32_t Ks[32][36];    // K [key][dh-pair]
    __shared__ uint32_t Vt[64][18];    // V^T [dh][key-pair]

    const int bh   = blockIdx.y;
    const int qt   = (Ln / 64 - 1) - blockIdx.x;   // longest-first (LPT)
    const int qbase = qt * 64;
    const int tid  = threadIdx.x;
    const int lane = tid & 31;
    const int warp = tid >> 5;

    const float qscale = 0.125f * 1.4426950408889634f;  // (1/sqrt64)*log2(e)

    // ---- stage Q (fp16 source; unpack, scale, repack; once per block) ----
    {
        const __half* qg = g_q + ((size_t)bh * Ln + qbase) * DHn;
        #pragma unroll
        for (int i = 0; i < 8; i++) {
            int idx = i * 128 + tid;          // 1024 uint2
            int row = idx >> 4, c4 = idx & 15;
            uint2 u = *(const uint2*)(qg + (size_t)row * DHn + c4 * 4);
            float2 f0 = __half22float2(*(__half2*)&u.x);
            float2 f1 = __half22float2(*(__half2*)&u.y);
            uint2 o = { pack_h2(f0.x * qscale, f0.y * qscale),
                        pack_h2(f1.x * qscale, f1.y * qscale) };
            *(uint2*)&QP[row][c4 * 2] = o;
        }
    }
    __syncthreads();

    // ---- build Q fragments (held in regs): 4 k16 chunks ----
    const int r0 = warp * 16 + (lane >> 2);
    uint32_t qf[4][4];
    #pragma unroll
    for (int kc = 0; kc < 4; kc++) {
        int c = kc * 8 + (lane & 3);
        qf[kc][0] = QP[r0][c];
        qf[kc][1] = QP[r0 + 8][c];
        qf[kc][2] = QP[r0][c + 4];
        qf[kc][3] = QP[r0 + 8][c + 4];
    }

    float m0 = -1e30f, m1 = -1e30f, l0 = 0.f, l1 = 0.f;
    float oacc[8][4];
    #pragma unroll
    for (int nt = 0; nt < 8; nt++)
        #pragma unroll
        for (int i = 0; i < 4; i++) oacc[nt][i] = 0.f;

    const __half* kg = g_k + (size_t)bh * Ln * DHn;
    const __half* vg = g_v + (size_t)bh * Ln * DHn;
    const int grow0 = qbase + warp * 16 + (lane >> 2);
    const int grow1 = grow0 + 8;

    // loader coords: 4 uint2 (4 halfs) of K and of V per thread per tile
    const int ldrow = tid >> 4;          // base key row 0..7 (stride 8)
    const int ldc4  = tid & 15;          // 4-half column (dh/4)

    // ---- prefetch tile 0 ----
    uint2 pk[4], pv[4];
    #pragma unroll
    for (int i = 0; i < 4; i++) {
        size_t g = ((size_t)(ldrow + i * 8)) * DHn + ldc4 * 4;
        pk[i] = *(const uint2*)(kg + g);
        pv[i] = *(const uint2*)(vg + g);
    }

    const int nkt = 2 * qt + 2;
    for (int kt = 0; kt < nkt; kt++) {
        __syncthreads();   // previous tile's smem reads complete
        // ---- commit prefetched tile: K raw copy; V transposed (halfs) ----
        #pragma unroll
        for (int i = 0; i < 4; i++) {
            int key = ldrow + i * 8;
            *(uint2*)&Ks[key][ldc4 * 2] = pk[i];
            __half* vh = (__half*)Vt;         // stride 36 halfs per dh row
            const __half* h = (const __half*)&pv[i];
            int dh = ldc4 * 4;
            vh[(dh + 0) * 36 + key] = h[0];
            vh[(dh + 1) * 36 + key] = h[1];
            vh[(dh + 2) * 36 + key] = h[2];
            vh[(dh + 3) * 36 + key] = h[3];
        }
        __syncthreads();

        // ---- prefetch next tile (overlaps compute) ----
        if (kt + 1 < nkt) {
            #pragma unroll
            for (int i = 0; i < 4; i++) {
                size_t g = ((size_t)((kt + 1) * 32 + ldrow + i * 8)) * DHn + ldc4 * 4;
                pk[i] = *(const uint2*)(kg + g);
                pv[i] = *(const uint2*)(vg + g);
            }
        }

        // ---- S = Q @ K^T  (16 q-rows x 32 keys per warp) ----
        float sacc[4][4];
        #pragma unroll
        for (int nt = 0; nt < 4; nt++)
            #pragma unroll
            for (int i = 0; i < 4; i++) sacc[nt][i] = 0.f;

        #pragma unroll
        for (int kc = 0; kc < 4; kc++) {
            const int c = kc * 8 + (lane & 3);
            uint32_t kf[4][2];
            #pragma unroll
            for (int nt = 0; nt < 4; nt++) {
                int n = nt * 8 + (lane >> 2);
                kf[nt][0] = Ks[n][c];
                kf[nt][1] = Ks[n][c + 4];
            }
            #pragma unroll
            for (int nt = 0; nt < 4; nt++)
                mma_f16(sacc[nt], qf[kc], kf[nt]);
        }

        // ---- causal mask (only near the diagonal) ----
        if (kt * 32 + 31 > qbase + warp * 16) {
            #pragma unroll
            for (int nt = 0; nt < 4; nt++) {
                int gc0 = kt * 32 + nt * 8 + 2 * (lane & 3);
                int gc1 = gc0 + 1;
                if (gc0 > grow0) sacc[nt][0] = -1e30f;
                if (gc1 > grow0) sacc[nt][1] = -1e30f;
                if (gc0 > grow1) sacc[nt][2] = -1e30f;
                if (gc1 > grow1) sacc[nt][3] = -1e30f;
            }
        }

        // ---- online softmax: row max over the 4-lane row group ----
        float tm0 = -1e30f, tm1 = -1e30f;
        #pragma unroll
        for (int nt = 0; nt < 4; nt++) {
            tm0 = fmaxf(tm0, fmaxf(sacc[nt][0], sacc[nt][1]));
            tm1 = fmaxf(tm1, fmaxf(sacc[nt][2], sacc[nt][3]));
        }
        tm0 = fmaxf(tm0, __shfl_xor_sync(0xffffffff, tm0, 1));
        tm0 = fmaxf(tm0, __shfl_xor_sync(0xffffffff, tm0, 2));
        tm1 = fmaxf(tm1, __shfl_xor_sync(0xffffffff, tm1, 1));
        tm1 = fmaxf(tm1, __shfl_xor_sync(0xffffffff, tm1, 2));

        float mn0 = fmaxf(m0, tm0), mn1 = fmaxf(m1, tm1);
        float sc0 = exp2f(m0 - mn0), sc1 = exp2f(m1 - mn1);
        m0 = mn0; m1 = mn1;
        l0 *= sc0; l1 *= sc1;
        #pragma unroll
        for (int nt = 0; nt < 8; nt++) {
            oacc[nt][0] *= sc0; oacc[nt][1] *= sc0;
            oacc[nt][2] *= sc1; oacc[nt][3] *= sc1;
        }

        // ---- p = exp2(s - m) -> fp16 pairs (packed along keys) into QP ----
        #pragma unroll
        for (int nt = 0; nt < 4; nt++) {
            int col = nt * 4 + (lane & 3);    // key-pair index
            uint32_t u0 = pack_h2(exp2f(sacc[nt][0] - mn0), exp2f(sacc[nt][1] - mn0));
            uint32_t u1 = pack_h2(exp2f(sacc[nt][2] - mn1), exp2f(sacc[nt][3] - mn1));
            float2 f0 = __half22float2(*(__half2*)&u0);
            float2 f1 = __half22float2(*(__half2*)&u1);
            l0 += f0.x + f0.y;
            l1 += f1.x + f1.y;
            QP[r0][col]     = u0;
            QP[r0 + 8][col] = u1;
        }
        __syncwarp();

        // ---- O += P @ V  (2 k16 chunks over 32 keys) ----
        #pragma unroll
        for (int kc = 0; kc < 2; kc++) {
            const int c = kc * 8 + (lane & 3);
            uint32_t pf[4];
            pf[0] = QP[r0][c];
            pf[1] = QP[r0 + 8][c];
            pf[2] = QP[r0][c + 4];
            pf[3] = QP[r0 + 8][c + 4];
            #pragma unroll
            for (int nt = 0; nt < 8; nt++) {
                int n = nt * 8 + (lane >> 2);    // dh index
                uint32_t vf[2];
                vf[0] = Vt[n][c];
                vf[1] = Vt[n][c + 4];
                mma_f16(oacc[nt], pf, vf);
            }
        }
        // (next iteration's __syncthreads protects P and K/V reuse)
    }

    // ---- epilogue ----
    l0 += __shfl_xor_sync(0xffffffff, l0, 1);
    l0 += __shfl_xor_sync(0xffffffff, l0, 2);
    l1 += __shfl_xor_sync(0xffffffff, l1, 1);
    l1 += __shfl_xor_sync(0xffffffff, l1, 2);
    float inv0 = 1.f / l0, inv1 = 1.f / l1;

    const int b = bh >> 4, h = bh & (Hn - 1);
    float* o0 = out + ((size_t)(b * Ln + grow0)) * Dn + h * DHn;
    float* o1 = out + ((size_t)(b * Ln + grow1)) * Dn + h * DHn;
    #pragma unroll
    for (int nt = 0; nt < 8; nt++) {
        int dh = nt * 8 + 2 * (lane & 3);
        float2 v0 = { oacc[nt][0] * inv0, oacc[nt][1] * inv0 };
        float2 v1 = { oacc[nt][2] * inv1, oacc[nt][3] * inv1 };
        *(float2*)(o0 + dh) = v0;
        *(float2*)(o1 + dh) = v1;
    }
}

// ---------------------------------------------------------------------------
// Launch. Inputs: x, atten_mask, Wq, bq, Wk, bk, Wv, bv. Mask is strict
// upper-triangular causal -> handled analytically.
// ---------------------------------------------------------------------------
extern "C" void kernel_launch(void* const* d_in, const int* in_sizes, int n_in,
                              void* d_out, int out_size)
{
    (void)in_sizes; (void)n_in; (void)out_size;
    const float* x  = (const float*)d_in[0];
    const float* Wq = (const float*)d_in[2];
    const float* bq = (const float*)d_in[3];
    const float* Wk = (const float*)d_in[4];
    const float* bk = (const float*)d_in[5];
    const float* Wv = (const float*)d_in[6];
    const float* bv = (const float*)d_in[7];
    float* out = (float*)d_out;

    __half* xh; cudaGetSymbolAddress((void**)&xh, g_xh);
    __half* wh; cudaGetSymbolAddress((void**)&wh, g_wh);

    cvt_f32_f16<<<2048, 256>>>(x,  xh,                        (Mrows * Dn) / 4);
    cvt_f32_f16<<<1024, 256>>>(Wq, wh + 0 * (size_t)Dn * Dn,  (Dn * Dn) / 4);
    cvt_f32_f16<<<1024, 256>>>(Wk, wh + 1 * (size_t)Dn * Dn,  (Dn * Dn) / 4);
    cvt_f32_f16<<<1024, 256>>>(Wv, wh + 2 * (size_t)Dn * Dn,  (Dn * Dn) / 4);

    qkv_gemm_f16<<<dim3(Dn / 128, Mrows / 128, 3), 256>>>(bq, bk, bv);
    attn_f16<<<dim3(Ln / 64, BHn), 128>>>(out);
}

// round 14
// speedup vs baseline: 1.4599x; 1.4599x over previous
#include <cuda_runtime.h>
#include <cuda_fp16.h>
#include <math.h>
#include <stdint.h>

// Problem constants
#define Bn  2
#define Ln  2048
#define Dn  1024
#define Hn  16
#define DHn 64
#define BHn (Bn*Hn)   // 32
#define Mrows (Bn*Ln) // 4096

// fp16 copies of inputs (prepass) + fp32 q/k/v scratch in [bh][l][dh].
__device__ __half g_xh[(size_t)Mrows*Dn];        // 8 MB
__device__ __half g_wh[3][(size_t)Dn*Dn];        // 6 MB
__device__ float g_q[(size_t)BHn*Ln*DHn];
__device__ float g_k[(size_t)BHn*Ln*DHn];
__device__ float g_v[(size_t)BHn*Ln*DHn];

// ---------------------------------------------------------------------------
// helpers
// ---------------------------------------------------------------------------
__device__ __forceinline__ uint32_t pack_h2(float x, float y) {
    __half2 h = __floats2half2_rn(x, y);
    return *(uint32_t*)&h;
}

__device__ __forceinline__ uint32_t smem_u32(const void* p) {
    return (uint32_t)__cvta_generic_to_shared(p);
}

// ldmatrix: 4x 8x8 b16 matrices, lane groups 0-7/8-15/16-23/24-31 -> r0..r3
__device__ __forceinline__ void ldsm_x4(uint32_t& r0, uint32_t& r1,
                                        uint32_t& r2, uint32_t& r3, uint32_t a) {
    asm volatile("ldmatrix.sync.aligned.m8n8.x4.shared.b16 {%0,%1,%2,%3}, [%4];"
        : "=r"(r0), "=r"(r1), "=r"(r2), "=r"(r3) : "r"(a));
}
__device__ __forceinline__ void ldsm_x4_t(uint32_t& r0, uint32_t& r1,
                                          uint32_t& r2, uint32_t& r3, uint32_t a) {
    asm volatile("ldmatrix.sync.aligned.m8n8.x4.trans.shared.b16 {%0,%1,%2,%3}, [%4];"
        : "=r"(r0), "=r"(r1), "=r"(r2), "=r"(r3) : "r"(a));
}

// D += A(16x16,row) * B(16x8,col), fp16 inputs, fp32 accum
__device__ __forceinline__ void mma_f16(float d[4], const uint32_t a[4], const uint32_t b[2]) {
    asm volatile(
        "mma.sync.aligned.m16n8k16.row.col.f32.f16.f16.f32 "
        "{%0,%1,%2,%3}, {%4,%5,%6,%7}, {%8,%9}, {%0,%1,%2,%3};\n"
        : "+f"(d[0]), "+f"(d[1]), "+f"(d[2]), "+f"(d[3])
        : "r"(a[0]), "r"(a[1]), "r"(a[2]), "r"(a[3]),
          "r"(b[0]), "r"(b[1]));
}

// ---------------------------------------------------------------------------
// Pre-pass: fp32 -> fp16 conversion (vectorized, grid-stride)
// ---------------------------------------------------------------------------
__global__ void cvt_f32_f16(const float* __restrict__ src, __half* __restrict__ dst, int n4)
{
    int i = blockIdx.x * blockDim.x + threadIdx.x;
    int stride = gridDim.x * blockDim.x;
    for (; i < n4; i += stride) {
        float4 v = ((const float4*)src)[i];
        uint2 u = { pack_h2(v.x, v.y), pack_h2(v.z, v.w) };
        *(uint2*)&dst[(size_t)i * 4] = u;
    }
}

// ---------------------------------------------------------------------------
// QKV projection: y = x @ W^T + b, fp16 inputs (prepass), fp32 scratch out.
// Round-12 geometry; fragment loads now via ldmatrix.x4 (bit-identical regs).
// ---------------------------------------------------------------------------
__global__ __launch_bounds__(256) void qkv_gemm_f16(
    const float* __restrict__ bq, const float* __restrict__ bk,
    const float* __restrict__ bv)
{
    __shared__ uint32_t As[128][20];   // 10 KB, row stride 80B (16B-aligned)
    __shared__ uint32_t Bs[128][20];   // 10 KB

    const __half* W = g_wh[blockIdx.z];
    const float* bias; float* dst;
    if (blockIdx.z == 0)      { bias = bq; dst = g_q; }
    else if (blockIdx.z == 1) { bias = bk; dst = g_k; }
    else                      { bias = bv; dst = g_v; }

    const int tid  = threadIdx.x;
    const int lane = tid & 31;
    const int warp = tid >> 5;
    const int wm   = warp >> 2;      // 0..1
    const int wn   = warp & 3;       // 0..3
    const int rowBase = blockIdx.y * 128;
    const int colBase = blockIdx.x * 128;

    // ldmatrix base addresses (bytes)
    // A: m0..m3 = rows {0-7, 8-15} x pairs {c, c+4}
    const uint32_t aAddr = smem_u32(&As[wm * 64 + (lane & 15)][(lane >> 4) << 2]);
    // B: m0..m3 = (nt0: pair c, c+4), (nt1: pair c, c+4)
    const uint32_t bAddr = smem_u32(&Bs[wn * 32 + (lane & 7) + ((lane >> 4) << 3)]
                                       [((lane >> 3) & 1) << 2]);

    float acc[4][4][4];
    #pragma unroll
    for (int mt = 0; mt < 4; mt++)
        #pragma unroll
        for (int nt = 0; nt < 4; nt++)
            #pragma unroll
            for (int i = 0; i < 4; i++) acc[mt][nt][i] = 0.f;

    for (int kb = 0; kb < Dn; kb += 32) {
        // loader: 4 iters x 256 threads = 1024 uint2 (4 halfs) per matrix
        uint2 a_reg[4], b_reg[4];
        #pragma unroll
        for (int i = 0; i < 4; i++) {
            int idx = i * 256 + tid;
            int row = idx >> 3, c4 = idx & 7;
            a_reg[i] = *(const uint2*)&g_xh[(size_t)(rowBase + row) * Dn + kb + c4 * 4];
            b_reg[i] = *(const uint2*)&W[(size_t)(colBase + row) * Dn + kb + c4 * 4];
        }
        __syncthreads();   // previous chunk's compute done before overwrite
        #pragma unroll
        for (int i = 0; i < 4; i++) {
            int idx = i * 256 + tid;
            int row = idx >> 3, c4 = idx & 7;
            *(uint2*)&As[row][c4 * 2] = a_reg[i];
            *(uint2*)&Bs[row][c4 * 2] = b_reg[i];
        }
        __syncthreads();

        #pragma unroll
        for (int kc = 0; kc < 2; kc++) {
            uint32_t af[4][4], bf[4][2];
            #pragma unroll
            for (int mt = 0; mt < 4; mt++)
                ldsm_x4(af[mt][0], af[mt][1], af[mt][2], af[mt][3],
                        aAddr + mt * (16 * 80) + kc * 32);
            #pragma unroll
            for (int j = 0; j < 2; j++)
                ldsm_x4(bf[2*j][0], bf[2*j][1], bf[2*j+1][0], bf[2*j+1][1],
                        bAddr + j * (16 * 80) + kc * 32);
            #pragma unroll
            for (int mt = 0; mt < 4; mt++)
                #pragma unroll
                for (int nt = 0; nt < 4; nt++)
                    mma_f16(acc[mt][nt], af[mt], bf[nt]);
        }
    }

    // epilogue: bias + head relayout into [bh][l][dh] (fp32 scratch)
    #pragma unroll
    for (int nt = 0; nt < 4; nt++) {
        int gcol = colBase + wn * 32 + nt * 8 + 2 * (lane & 3);
        int h  = gcol >> 6;
        int dh = gcol & (DHn - 1);
        float bb0 = bias[gcol], bb1 = bias[gcol + 1];
        #pragma unroll
        for (int mt = 0; mt < 4; mt++) {
            int grow = rowBase + wm * 64 + mt * 16 + (lane >> 2);
            {
                int b = grow >> 11, l = grow & (Ln - 1);
                float2 v = { acc[mt][nt][0] + bb0, acc[mt][nt][1] + bb1 };
                *(float2*)&dst[((size_t)(b * Hn + h) * Ln + l) * DHn + dh] = v;
            }
            {
                int grow2 = grow + 8;
                int b = grow2 >> 11, l = grow2 & (Ln - 1);
                float2 v = { acc[mt][nt][2] + bb0, acc[mt][nt][3] + bb1 };
                *(float2*)&dst[((size_t)(b * Hn + h) * Ln + l) * DHn + dh] = v;
            }
        }
    }
}

// ---------------------------------------------------------------------------
// Flash attention (causal), fp16 m16n8k16 MMA + register prefetch of K/V.
// Round-12 kernel with fragment loads via ldmatrix. V now committed key-major
// (same as K, conflict-free uint2) and transposed on load via ldmatrix.trans.
// Longest-first scheduling kept.
// ---------------------------------------------------------------------------
__global__ __launch_bounds__(128) void attn_f16(float* __restrict__ out)
{
    __shared__ uint32_t QP[64][36];    // Q (32 dh-pairs), later P (16 key-pairs)
    __shared__ uint32_t Ks[32][36];    // K [key][dh-pair], row stride 144B
    __shared__ uint32_t Vs[32][36];    // V [key][dh-pair] (transposed on load)

    const int bh   = blockIdx.y;
    const int qt   = (Ln / 64 - 1) - blockIdx.x;   // longest-first (LPT)
    const int qbase = qt * 64;
    const int tid  = threadIdx.x;
    const int lane = tid & 31;
    const int warp = tid >> 5;

    const float qscale = 0.125f * 1.4426950408889634f;  // (1/sqrt64)*log2(e)

    // ---- stage Q (prescaled, fp16 pairs along dh) ----
    {
        const float* qg = g_q + ((size_t)bh * Ln + qbase) * DHn;
        #pragma unroll
        for (int i = 0; i < 8; i++) {
            int idx = i * 128 + tid;          // 1024 float4
            int row = idx >> 4, c4 = idx & 15;
            float4 v = *(const float4*)(qg + (size_t)row * DHn + c4 * 4);
            uint2 u = { pack_h2(v.x * qscale, v.y * qscale),
                        pack_h2(v.z * qscale, v.w * qscale) };
            *(uint2*)&QP[row][c4 * 2] = u;
        }
    }
    __syncthreads();

    // ---- build Q fragments (held in regs): 4 k16 chunks ----
    const int r0 = warp * 16 + (lane >> 2);
    uint32_t qf[4][4];
    #pragma unroll
    for (int kc = 0; kc < 4; kc++) {
        int c = kc * 8 + (lane & 3);
        qf[kc][0] = QP[r0][c];
        qf[kc][1] = QP[r0 + 8][c];
        qf[kc][2] = QP[r0][c + 4];
        qf[kc][3] = QP[r0 + 8][c + 4];
    }

    // ldmatrix base addresses (bytes)
    // K (B-operand): m0..m3 = (nt0: pair c, c+4), (nt1: pair c, c+4)
    const uint32_t kAddr = smem_u32(&Ks[(lane & 7) + ((lane >> 4) << 3)]
                                       [((lane >> 3) & 1) << 2]);
    // P (A-operand): m0..m3 = rows {0-7, 8-15} x pairs {c, c+4}
    const uint32_t pAddr = smem_u32(&QP[warp * 16 + (lane & 15)][(lane >> 4) << 2]);
    // V (B-operand via trans): m0..m3 = (nt0: keys +0, +8), (nt1: keys +0, +8)
    const uint32_t vAddr = smem_u32(&Vs[(lane & 7) + ((lane >> 3) & 1) * 8][0])
                           + (((uint32_t)lane >> 4) << 4);   // dh halfs: +8 -> 16B

    float m0 = -1e30f, m1 = -1e30f, l0 = 0.f, l1 = 0.f;
    float oacc[8][4];
    #pragma unroll
    for (int nt = 0; nt < 8; nt++)
        #pragma unroll
        for (int i = 0; i < 4; i++) oacc[nt][i] = 0.f;

    const float* kg = g_k + (size_t)bh * Ln * DHn;
    const float* vg = g_v + (size_t)bh * Ln * DHn;
    const int grow0 = qbase + warp * 16 + (lane >> 2);
    const int grow1 = grow0 + 8;

    // loader coords: 4 float4 of K and V per thread per tile
    const int ldrow = tid >> 4;          // base key row 0..7 (stride 8)
    const int ldc4  = tid & 15;          // float4 column (dh/4)

    // ---- prefetch tile 0 ----
    float4 pk[4], pv[4];
    #pragma unroll
    for (int i = 0; i < 4; i++) {
        size_t g = ((size_t)(ldrow + i * 8)) * DHn + ldc4 * 4;
        pk[i] = *(const float4*)(kg + g);
        pv[i] = *(const float4*)(vg + g);
    }

    const int nkt = 2 * qt + 2;
    for (int kt = 0; kt < nkt; kt++) {
        __syncthreads();   // previous tile's smem reads complete
        // ---- commit prefetched tile: K and V both key-major, uint2 ----
        #pragma unroll
        for (int i = 0; i < 4; i++) {
            int key = ldrow + i * 8;
            uint2 uk = { pack_h2(pk[i].x, pk[i].y), pack_h2(pk[i].z, pk[i].w) };
            uint2 uv = { pack_h2(pv[i].x, pv[i].y), pack_h2(pv[i].z, pv[i].w) };
            *(uint2*)&Ks[key][ldc4 * 2] = uk;
            *(uint2*)&Vs[key][ldc4 * 2] = uv;
        }
        __syncthreads();

        // ---- prefetch next tile (overlaps compute) ----
        if (kt + 1 < nkt) {
            #pragma unroll
            for (int i = 0; i < 4; i++) {
                size_t g = ((size_t)((kt + 1) * 32 + ldrow + i * 8)) * DHn + ldc4 * 4;
                pk[i] = *(const float4*)(kg + g);
                pv[i] = *(const float4*)(vg + g);
            }
        }

        // ---- S = Q @ K^T  (16 q-rows x 32 keys per warp) ----
        float sacc[4][4];
        #pragma unroll
        for (int nt = 0; nt < 4; nt++)
            #pragma unroll
            for (int i = 0; i < 4; i++) sacc[nt][i] = 0.f;

        #pragma unroll
        for (int kc = 0; kc < 4; kc++) {
            uint32_t kf[4][2];
            #pragma unroll
            for (int j = 0; j < 2; j++)
                ldsm_x4(kf[2*j][0], kf[2*j][1], kf[2*j+1][0], kf[2*j+1][1],
                        kAddr + j * (16 * 144) + kc * 32);
            #pragma unroll
            for (int nt = 0; nt < 4; nt++)
                mma_f16(sacc[nt], qf[kc], kf[nt]);
        }

        // ---- causal mask (only near the diagonal) ----
        if (kt * 32 + 31 > qbase + warp * 16) {
            #pragma unroll
            for (int nt = 0; nt < 4; nt++) {
                int gc0 = kt * 32 + nt * 8 + 2 * (lane & 3);
                int gc1 = gc0 + 1;
                if (gc0 > grow0) sacc[nt][0] = -1e30f;
                if (gc1 > grow0) sacc[nt][1] = -1e30f;
                if (gc0 > grow1) sacc[nt][2] = -1e30f;
                if (gc1 > grow1) sacc[nt][3] = -1e30f;
            }
        }

        // ---- online softmax: row max over the 4-lane row group ----
        float tm0 = -1e30f, tm1 = -1e30f;
        #pragma unroll
        for (int nt = 0; nt < 4; nt++) {
            tm0 = fmaxf(tm0, fmaxf(sacc[nt][0], sacc[nt][1]));
            tm1 = fmaxf(tm1, fmaxf(sacc[nt][2], sacc[nt][3]));
        }
        tm0 = fmaxf(tm0, __shfl_xor_sync(0xffffffff, tm0, 1));
        tm0 = fmaxf(tm0, __shfl_xor_sync(0xffffffff, tm0, 2));
        tm1 = fmaxf(tm1, __shfl_xor_sync(0xffffffff, tm1, 1));
        tm1 = fmaxf(tm1, __shfl_xor_sync(0xffffffff, tm1, 2));

        float mn0 = fmaxf(m0, tm0), mn1 = fmaxf(m1, tm1);
        float sc0 = exp2f(m0 - mn0), sc1 = exp2f(m1 - mn1);
        m0 = mn0; m1 = mn1;
        l0 *= sc0; l1 *= sc1;
        #pragma unroll
        for (int nt = 0; nt < 8; nt++) {
            oacc[nt][0] *= sc0; oacc[nt][1] *= sc0;
            oacc[nt][2] *= sc1; oacc[nt][3] *= sc1;
        }

        // ---- p = exp2(s - m) -> fp16 pairs (packed along keys) into QP ----
        #pragma unroll
        for (int nt = 0; nt < 4; nt++) {
            int col = nt * 4 + (lane & 3);    // key-pair index
            uint32_t u0 = pack_h2(exp2f(sacc[nt][0] - mn0), exp2f(sacc[nt][1] - mn0));
            uint32_t u1 = pack_h2(exp2f(sacc[nt][2] - mn1), exp2f(sacc[nt][3] - mn1));
            float2 f0 = __half22float2(*(__half2*)&u0);
            float2 f1 = __half22float2(*(__half2*)&u1);
            l0 += f0.x + f0.y;
            l1 += f1.x + f1.y;
            QP[r0][col]     = u0;
            QP[r0 + 8][col] = u1;
        }
        __syncwarp();

        // ---- O += P @ V  (2 k16 chunks over 32 keys) ----
        #pragma unroll
        for (int kc = 0; kc < 2; kc++) {
            uint32_t pf[4];
            ldsm_x4(pf[0], pf[1], pf[2], pf[3], pAddr + kc * 32);
            #pragma unroll
            for (int j = 0; j < 4; j++) {
                uint32_t vf0[2], vf1[2];
                ldsm_x4_t(vf0[0], vf0[1], vf1[0], vf1[1],
                          vAddr + kc * (16 * 144) + j * 32);
                mma_f16(oacc[2*j],     pf, vf0);
                mma_f16(oacc[2*j + 1], pf, vf1);
            }
        }
        // (next iteration's __syncthreads protects P and K/V reuse)
    }

    // ---- epilogue ----
    l0 += __shfl_xor_sync(0xffffffff, l0, 1);
    l0 += __shfl_xor_sync(0xffffffff, l0, 2);
    l1 += __shfl_xor_sync(0xffffffff, l1, 1);
    l1 += __shfl_xor_sync(0xffffffff, l1, 2);
    float inv0 = 1.f / l0, inv1 = 1.f / l1;

    const int b = bh >> 4, h = bh & (Hn - 1);
    float* o0 = out + ((size_t)(b * Ln + grow0)) * Dn + h * DHn;
    float* o1 = out + ((size_t)(b * Ln + grow1)) * Dn + h * DHn;
    #pragma unroll
    for (int nt = 0; nt < 8; nt++) {
        int dh = nt * 8 + 2 * (lane & 3);
        float2 v0 = { oacc[nt][0] * inv0, oacc[nt][1] * inv0 };
        float2 v1 = { oacc[nt][2] * inv1, oacc[nt][3] * inv1 };
        *(float2*)(o0 + dh) = v0;
        *(float2*)(o1 + dh) = v1;
    }
}

// ---------------------------------------------------------------------------
// Launch. Inputs: x, atten_mask, Wq, bq, Wk, bk, Wv, bv. Mask is strict
// upper-triangular causal -> handled analytically.
// ---------------------------------------------------------------------------
extern "C" void kernel_launch(void* const* d_in, const int* in_sizes, int n_in,
                              void* d_out, int out_size)
{
    (void)in_sizes; (void)n_in; (void)out_size;
    const float* x  = (const float*)d_in[0];
    const float* Wq = (const float*)d_in[2];
    const float* bq = (const float*)d_in[3];
    const float* Wk = (const float*)d_in[4];
    const float* bk = (const float*)d_in[5];
    const float* Wv = (const float*)d_in[6];
    const float* bv = (const float*)d_in[7];
    float* out = (float*)d_out;

    __half* xh; cudaGetSymbolAddress((void**)&xh, g_xh);
    __half* wh; cudaGetSymbolAddress((void**)&wh, g_wh);

    cvt_f32_f16<<<2048, 256>>>(x,  xh,                        (Mrows * Dn) / 4);
    cvt_f32_f16<<<1024, 256>>>(Wq, wh + 0 * (size_t)Dn * Dn,  (Dn * Dn) / 4);
    cvt_f32_f16<<<1024, 256>>>(Wk, wh + 1 * (size_t)Dn * Dn,  (Dn * Dn) / 4);
    cvt_f32_f16<<<1024, 256>>>(Wv, wh + 2 * (size_t)Dn * Dn,  (Dn * Dn) / 4);

    qkv_gemm_f16<<<dim3(Dn / 128, Mrows / 128, 3), 256>>>(bq, bk, bv);
    attn_f16<<<dim3(Ln / 64, BHn), 128>>>(out);
}